// round 6
// baseline (speedup 1.0000x reference)
#include <cuda_runtime.h>
#include <stdint.h>

#define B_     4
#define CDIM   512
#define LSEQ   2048
#define HEADS_ 8
#define DHEAD  64
#define HID    512
#define O3     1536
#define QSCALE 0.125f

typedef uint32_t u32;

// ------------------------- scratch (device globals) -------------------------
__device__ float    g_qkv[(size_t)B_ * O3 * LSEQ];    // [b][o][l], q pre-scaled
__device__ uint16_t g_xh[(size_t)B_ * CDIM * LSEQ];   // x bf16 hi/lo
__device__ uint16_t g_xl[(size_t)B_ * CDIM * LSEQ];
__device__ uint16_t g_wqh[O3 * CDIM], g_wql[O3 * CDIM];
__device__ uint16_t g_woh[CDIM * HID], g_wol[CDIM * HID];
__device__ uint16_t g_qh[(size_t)B_ * HEADS_ * LSEQ * DHEAD]; // [b][h][l][d]
__device__ uint16_t g_ql[(size_t)B_ * HEADS_ * LSEQ * DHEAD];
__device__ uint16_t g_kh[(size_t)B_ * HEADS_ * LSEQ * DHEAD];
__device__ uint16_t g_kl[(size_t)B_ * HEADS_ * LSEQ * DHEAD];
__device__ uint16_t g_vh[(size_t)B_ * HEADS_ * DHEAD * LSEQ]; // [b][h][d][l]
__device__ uint16_t g_vl[(size_t)B_ * HEADS_ * DHEAD * LSEQ];
__device__ uint16_t g_ath[(size_t)B_ * HID * LSEQ];   // attention out bf16 hi/lo
__device__ uint16_t g_atl[(size_t)B_ * HID * LSEQ];

// ------------------------------- helpers -------------------------------------
__device__ __forceinline__ u32 smem_u32(const void* p) {
    u32 a; asm("{ .reg .u64 t; cvta.to.shared.u64 t, %1; cvt.u32.u64 %0, t; }"
               : "=r"(a) : "l"(p));
    return a;
}
__device__ __forceinline__ u32 pack_bf16x2(float a, float b) {
    u32 r; asm("cvt.rn.bf16x2.f32 %0, %1, %2;" : "=r"(r) : "f"(b), "f"(a));
    return r;
}
__device__ __forceinline__ float bf_lo(u32 w) { return __uint_as_float(w << 16); }
__device__ __forceinline__ float bf_hi(u32 w) { return __uint_as_float(w & 0xffff0000u); }
__device__ __forceinline__ void split_pair(float a, float b, u32& hw, u32& lw) {
    hw = pack_bf16x2(a, b);
    lw = pack_bf16x2(a - bf_lo(hw), b - bf_hi(hw));
}
__device__ __forceinline__ void mma_bf(float c[4], const u32 a[4], u32 b0, u32 b1) {
    asm volatile(
        "mma.sync.aligned.m16n8k16.row.col.f32.bf16.bf16.f32 "
        "{%0,%1,%2,%3}, {%4,%5,%6,%7}, {%8,%9}, {%0,%1,%2,%3};"
        : "+f"(c[0]), "+f"(c[1]), "+f"(c[2]), "+f"(c[3])
        : "r"(a[0]), "r"(a[1]), "r"(a[2]), "r"(a[3]), "r"(b0), "r"(b1));
}
__device__ __forceinline__ void ldsm4(u32 r[4], u32 addr) {
    asm volatile("ldmatrix.sync.aligned.m8n8.x4.shared.b16 {%0,%1,%2,%3}, [%4];"
        : "=r"(r[0]), "=r"(r[1]), "=r"(r[2]), "=r"(r[3]) : "r"(addr));
}
__device__ __forceinline__ void ldsm4t(u32 r[4], u32 addr) {
    asm volatile("ldmatrix.sync.aligned.m8n8.x4.trans.shared.b16 {%0,%1,%2,%3}, [%4];"
        : "=r"(r[0]), "=r"(r[1]), "=r"(r[2]), "=r"(r[3]) : "r"(addr));
}
__device__ __forceinline__ void cp16(u32 dst, const void* src) {
    asm volatile("cp.async.cg.shared.global [%0], [%1], 16;" :: "r"(dst), "l"(src));
}
#define CP_COMMIT() asm volatile("cp.async.commit_group;" ::: "memory")
#define CP_WAIT0()  asm volatile("cp.async.wait_group 0;" ::: "memory")

// ---------------------------------------------------------------------------
// split_scale: fp32 -> bf16 hi/lo arrays; first q4 float4-groups scaled
// ---------------------------------------------------------------------------
__global__ __launch_bounds__(256) void split_scale(
    const float* __restrict__ in, uint16_t* __restrict__ oh,
    uint16_t* __restrict__ ol, int n4, int q4)
{
    int i = blockIdx.x * 256 + threadIdx.x;
    if (i >= n4) return;
    float4 v = ((const float4*)in)[i];
    float sc = (i < q4) ? QSCALE : 1.0f;
    v.x *= sc; v.y *= sc; v.z *= sc; v.w *= sc;
    u32 h0, l0, h1, l1;
    split_pair(v.x, v.y, h0, l0);
    split_pair(v.z, v.w, h1, l1);
    ((uint2*)oh)[i] = make_uint2(h0, h1);
    ((uint2*)ol)[i] = make_uint2(l0, l1);
}

// ---------------------------------------------------------------------------
// Pipelined bf16-split GEMM: C[b][m][n] = sum_k A[m][k]*B[b][k][n] (+bias)
// A/B pre-split bf16 in global. cp.async double-buffered smem, TK=32.
// CTA 128x128, 8 warps (4m x 2n); 3-term: AhBh + AhBl + AlBh.
// ---------------------------------------------------------------------------
#define PKA 40    // A pitch bf16 (80B rows)
#define PNB 136   // B pitch bf16 (272B rows)
#define G_ASZ (128 * PKA * 2)          // 10240 B per A array
#define G_BSZ (32 * PNB * 2)           // 8704 B per B array
#define G_STG (2 * G_ASZ + 2 * G_BSZ)  // 37888 B per stage
#define GEMM_SMEM (2 * G_STG)          // 75776 B

__global__ __launch_bounds__(256) void gemm_bfp(
    const uint16_t* __restrict__ Ahg, const uint16_t* __restrict__ Alg,
    const uint16_t* __restrict__ Bhg, const uint16_t* __restrict__ Blg,
    float* __restrict__ C, const float* __restrict__ bias,
    int N, int K, long strideB, long strideC)
{
    extern __shared__ char smp[];
    const u32 sb = smem_u32(smp);

    const int tid = threadIdx.x;
    const int lane = tid & 31, wid = tid >> 5;
    const int lam = lane & 3, g = lane >> 2;
    const int fr = lane & 15, fc = (lane >> 4) * 8;
    const int wm = (wid & 3) * 32, wn = (wid >> 2) * 64;
    const int m0 = blockIdx.y * 128, n0 = blockIdx.x * 128;
    const uint16_t* Bh_b = Bhg + (size_t)blockIdx.z * strideB;
    const uint16_t* Bl_b = Blg + (size_t)blockIdx.z * strideB;
    float* Cb = C + (size_t)blockIdx.z * strideC;

    const int NS = K / 32;

    // cp.async issue of one k-slice into stage st
    auto issue = [&](int st, int k0) {
        u32 base = sb + st * G_STG;
#pragma unroll
        for (int j = 0; j < 2; j++) {
            int c = tid * 2 + j;                  // 0..511
            int ar = c >> 2, ac = c & 3;          // A: m row, 16B chunk
            const size_t aoff = (size_t)(m0 + ar) * K + k0 + ac * 8;
            cp16(base + ar * 80 + ac * 16, Ahg + aoff);
            cp16(base + G_ASZ + ar * 80 + ac * 16, Alg + aoff);
            int br = c >> 4, bc = c & 15;         // B: k row, 16B chunk
            const size_t boff = (size_t)(k0 + br) * N + n0 + bc * 8;
            cp16(base + 2 * G_ASZ + br * 272 + bc * 16, Bh_b + boff);
            cp16(base + 2 * G_ASZ + G_BSZ + br * 272 + bc * 16, Bl_b + boff);
        }
    };

    float acc[2][8][4];
#pragma unroll
    for (int mt = 0; mt < 2; mt++)
#pragma unroll
        for (int nt = 0; nt < 8; nt++)
#pragma unroll
            for (int r = 0; r < 4; r++) acc[mt][nt][r] = 0.f;

    issue(0, 0);
    CP_COMMIT();

    for (int s = 0; s < NS; s++) {
        CP_WAIT0();
        __syncthreads();
        if (s + 1 < NS) { issue((s + 1) & 1, (s + 1) * 32); CP_COMMIT(); }

        const u32 aB = sb + (s & 1) * G_STG;
        const u32 alB = aB + G_ASZ;
        const u32 bB = aB + 2 * G_ASZ;
        const u32 blB = bB + G_BSZ;

#pragma unroll
        for (int ks = 0; ks < 2; ks++) {
            u32 ahf[2][4], alf[2][4];
#pragma unroll
            for (int mt = 0; mt < 2; mt++) {
                u32 off = (u32)((wm + mt * 16 + fr) * PKA + ks * 16 + fc) * 2;
                ldsm4(ahf[mt], aB + off);
                ldsm4(alf[mt], alB + off);
            }
#pragma unroll
            for (int ntp = 0; ntp < 4; ntp++) {
                u32 bhf[4], blf[4];
                u32 off = (u32)((ks * 16 + fr) * PNB + wn + ntp * 16 + fc) * 2;
                ldsm4t(bhf, bB + off);
                ldsm4t(blf, blB + off);
#pragma unroll
                for (int mt = 0; mt < 2; mt++) {
                    mma_bf(acc[mt][2 * ntp],     ahf[mt], bhf[0], bhf[1]);
                    mma_bf(acc[mt][2 * ntp + 1], ahf[mt], bhf[2], bhf[3]);
                    mma_bf(acc[mt][2 * ntp],     ahf[mt], blf[0], blf[1]);
                    mma_bf(acc[mt][2 * ntp + 1], ahf[mt], blf[2], blf[3]);
                    mma_bf(acc[mt][2 * ntp],     alf[mt], bhf[0], bhf[1]);
                    mma_bf(acc[mt][2 * ntp + 1], alf[mt], bhf[2], bhf[3]);
                }
            }
        }
    }

#pragma unroll
    for (int mt = 0; mt < 2; mt++) {
#pragma unroll
        for (int r = 0; r < 2; r++) {
            int m = m0 + wm + mt * 16 + g + r * 8;
            float bv = bias ? bias[m] : 0.0f;
            float* Crow = Cb + (size_t)m * N + n0 + wn;
#pragma unroll
            for (int nt = 0; nt < 8; nt++) {
                float2 o;
                o.x = acc[mt][nt][r * 2 + 0] + bv;
                o.y = acc[mt][nt][r * 2 + 1] + bv;
                *(float2*)(Crow + nt * 8 + lam * 2) = o;
            }
        }
    }
}

// ---------------------------------------------------------------------------
// Convert Q/K: qkv fp32 [b][o][l] -> [b][h][l][d] bf16 hi/lo (transpose d,l)
// ---------------------------------------------------------------------------
__global__ __launch_bounds__(256) void conv_qk(const float* __restrict__ qkv)
{
    __shared__ float tile[64][65];
    const int tid = threadIdx.x;
    const int bh = blockIdx.y;
    const int b = bh >> 3, h = bh & 7;
    const int l0 = blockIdx.x * 64;
    const int zb = blockIdx.z * HID;

    const float* src = qkv + ((size_t)b * O3 + zb + h * DHEAD) * LSEQ + l0;
#pragma unroll
    for (int e = tid; e < 4096; e += 256) {
        int d = e >> 6, l = e & 63;
        tile[d][l] = src[(size_t)d * LSEQ + l];
    }
    __syncthreads();

    u32* dh = (u32*)(blockIdx.z ? g_kh : g_qh);
    u32* dl = (u32*)(blockIdx.z ? g_kl : g_ql);
    const size_t rowbase = ((size_t)bh * LSEQ + l0) * 32;
#pragma unroll
    for (int e = tid; e < 2048; e += 256) {
        int l = e >> 5, dp = e & 31;
        float a = tile[dp * 2][l], c = tile[dp * 2 + 1][l];
        u32 hw, lw; split_pair(a, c, hw, lw);
        dh[rowbase + (size_t)l * 32 + dp] = hw;
        dl[rowbase + (size_t)l * 32 + dp] = lw;
    }
}

__global__ __launch_bounds__(256) void conv_v(const float* __restrict__ qkv)
{
    size_t i4 = (size_t)blockIdx.x * 256 + threadIdx.x;
    size_t i = i4 * 4;
    size_t b = i >> 20, rem = i & ((1u << 20) - 1);
    float4 v = *(const float4*)(qkv + ((size_t)b * O3 + 2 * HID) * LSEQ + rem);
    u32 h0, l0, h1, l1;
    split_pair(v.x, v.y, h0, l0);
    split_pair(v.z, v.w, h1, l1);
    ((uint2*)g_vh)[i4] = make_uint2(h0, h1);
    ((uint2*)g_vl)[i4] = make_uint2(l0, l1);
}

// ---------------------------------------------------------------------------
// Flash attention, cp.async double-buffered K/V; bf16 hi/lo output.
// CTA = 128 queries of one (b,h); 8 warps x 16 q; key blocks of 128.
// ---------------------------------------------------------------------------
#define PD  72    // Q/K pitch (144B rows)
#define PV  136   // V pitch (272B rows)
#define POT 132   // O^T fp32 staging pitch

#define F_Q   (128 * PD * 2)             // 18432 per Q array
#define F_KSZ (128 * PD * 2)             // 18432 per K array
#define F_VSZ (64 * PV * 2)              // 17408 per V array
#define F_STG (2 * F_KSZ + 2 * F_VSZ)    // 71680 per stage
#define F_ST0 (2 * F_Q)                  // 36864
#define FLASH_SMEM (F_ST0 + 2 * F_STG)   // 180224

__global__ __launch_bounds__(256, 1) void flash_mma(void)
{
    extern __shared__ char smc[];
    const u32 sb = smem_u32(smc);

    const int tid = threadIdx.x;
    const int lane = tid & 31, wid = tid >> 5;
    const int g = lane >> 2, lam = lane & 3;
    const int fr = lane & 15, fc = (lane >> 4) * 8;
    const int bh = blockIdx.y;
    const int q0 = blockIdx.x * 128;

    const uint16_t* kh = g_kh + (size_t)bh * LSEQ * DHEAD;
    const uint16_t* kl = g_kl + (size_t)bh * LSEQ * DHEAD;
    const uint16_t* vh = g_vh + (size_t)bh * DHEAD * LSEQ;
    const uint16_t* vl = g_vl + (size_t)bh * DHEAD * LSEQ;

    auto issueKV = [&](int st, int n0) {
        u32 base = sb + F_ST0 + st * F_STG;
#pragma unroll
        for (int j = 0; j < 4; j++) {
            int c = tid * 4 + j;                 // 0..1023
            int kr = c >> 3, kc = c & 7;
            const size_t koff = (size_t)(n0 + kr) * DHEAD + kc * 8;
            cp16(base + kr * 144 + kc * 16, kh + koff);
            cp16(base + F_KSZ + kr * 144 + kc * 16, kl + koff);
            int vr = c >> 4, vc = c & 15;
            const size_t voff = (size_t)vr * LSEQ + n0 + vc * 8;
            cp16(base + 2 * F_KSZ + vr * 272 + vc * 16, vh + voff);
            cp16(base + 2 * F_KSZ + F_VSZ + vr * 272 + vc * 16, vl + voff);
        }
    };

    issueKV(0, 0);
    CP_COMMIT();

    // stage Q (plain loads; overlaps with in-flight cp.async)
    {
        uint16_t* Qh = (uint16_t*)smc;
        uint16_t* Ql = (uint16_t*)(smc + F_Q);
        const uint16_t* qh = g_qh + ((size_t)bh * LSEQ + q0) * DHEAD;
        const uint16_t* ql = g_ql + ((size_t)bh * LSEQ + q0) * DHEAD;
#pragma unroll
        for (int it = tid; it < 1024; it += 256) {
            int r = it >> 3, c = it & 7;
            *(uint4*)&Qh[r * PD + c * 8] = *(const uint4*)(qh + (size_t)r * 64 + c * 8);
            *(uint4*)&Ql[r * PD + c * 8] = *(const uint4*)(ql + (size_t)r * 64 + c * 8);
        }
    }

    float o[8][4];
#pragma unroll
    for (int nt = 0; nt < 8; nt++)
#pragma unroll
        for (int r = 0; r < 4; r++) o[nt][r] = 0.f;
    float rs0 = 0.f, rs1 = 0.f;

    for (int blk = 0; blk < 16; blk++) {
        CP_WAIT0();
        __syncthreads();
        if (blk < 15) { issueKV((blk + 1) & 1, (blk + 1) * 128); CP_COMMIT(); }

        const u32 kB = sb + F_ST0 + (blk & 1) * F_STG;
        const u32 klB = kB + F_KSZ;
        const u32 vB = kB + 2 * F_KSZ;
        const u32 vlB = vB + F_VSZ;
        const u32 qB = sb, qlB = sb + F_Q;

        // ---- S = Q K^T (16 q x 128 key), 3-term split
        float s[16][4];
#pragma unroll
        for (int nt = 0; nt < 16; nt++)
#pragma unroll
            for (int r = 0; r < 4; r++) s[nt][r] = 0.f;

#pragma unroll
        for (int ks = 0; ks < 4; ks++) {
            u32 qhf[4], qlf[4];
            u32 qoff = (u32)((wid * 16 + fr) * PD + ks * 16 + fc) * 2;
            ldsm4(qhf, qB + qoff);
            ldsm4(qlf, qlB + qoff);
#pragma unroll
            for (int ntp = 0; ntp < 8; ntp++) {
                u32 khf[4], klf[4];
                u32 koff = (u32)((ntp * 16 + fr) * PD + ks * 16 + fc) * 2;
                ldsm4(khf, kB + koff);
                ldsm4(klf, klB + koff);
                mma_bf(s[2 * ntp],     qhf, khf[0], khf[2]);
                mma_bf(s[2 * ntp + 1], qhf, khf[1], khf[3]);
                mma_bf(s[2 * ntp],     qhf, klf[0], klf[2]);
                mma_bf(s[2 * ntp + 1], qhf, klf[1], klf[3]);
                mma_bf(s[2 * ntp],     qlf, khf[0], khf[2]);
                mma_bf(s[2 * ntp + 1], qlf, khf[1], khf[3]);
            }
        }

        // ---- exp (no max subtraction) + row-sum partials
#pragma unroll
        for (int nt = 0; nt < 16; nt++) {
            s[nt][0] = __expf(s[nt][0]);
            s[nt][1] = __expf(s[nt][1]);
            s[nt][2] = __expf(s[nt][2]);
            s[nt][3] = __expf(s[nt][3]);
            rs0 += s[nt][0] + s[nt][1];
            rs1 += s[nt][2] + s[nt][3];
        }

        // ---- O += P V : P fragments from S registers
#pragma unroll
        for (int ks2 = 0; ks2 < 8; ks2++) {
            int t = ks2 * 2;
            u32 pa[4], pl[4];
            split_pair(s[t][0],     s[t][1],     pa[0], pl[0]);
            split_pair(s[t][2],     s[t][3],     pa[1], pl[1]);
            split_pair(s[t + 1][0], s[t + 1][1], pa[2], pl[2]);
            split_pair(s[t + 1][2], s[t + 1][3], pa[3], pl[3]);
#pragma unroll
            for (int dp = 0; dp < 4; dp++) {
                u32 vhf[4], vlf[4];
                u32 voff = (u32)((dp * 16 + fr) * PV + ks2 * 16 + fc) * 2;
                ldsm4(vhf, vB + voff);
                ldsm4(vlf, vlB + voff);
                mma_bf(o[2 * dp],     pa, vhf[0], vhf[2]);
                mma_bf(o[2 * dp + 1], pa, vhf[1], vhf[3]);
                mma_bf(o[2 * dp],     pa, vlf[0], vlf[2]);
                mma_bf(o[2 * dp + 1], pa, vlf[1], vlf[3]);
                mma_bf(o[2 * dp],     pl, vhf[0], vhf[2]);
                mma_bf(o[2 * dp + 1], pl, vhf[1], vhf[3]);
            }
        }
    }

    // normalize (row sums live in the 4 lam lanes of each quad)
    rs0 += __shfl_xor_sync(0xffffffffu, rs0, 1);
    rs0 += __shfl_xor_sync(0xffffffffu, rs0, 2);
    rs1 += __shfl_xor_sync(0xffffffffu, rs1, 1);
    rs1 += __shfl_xor_sync(0xffffffffu, rs1, 2);
    const float inv0 = 1.0f / rs0, inv1 = 1.0f / rs1;

    // O^T to smem [d][q] (reuse stage0 area; safe: disjoint from stage1 reads)
    float* Ot = (float*)(smc + F_ST0);
#pragma unroll
    for (int nt = 0; nt < 8; nt++) {
        int d = nt * 8 + 2 * lam;
        int q = wid * 16 + g;
        Ot[d * POT + q]           = o[nt][0] * inv0;
        Ot[(d + 1) * POT + q]     = o[nt][1] * inv0;
        Ot[d * POT + q + 8]       = o[nt][2] * inv1;
        Ot[(d + 1) * POT + q + 8] = o[nt][3] * inv1;
    }
    __syncthreads();

    // write att as bf16 hi/lo, [b][h*64+d][l]
    const int b = bh >> 3, h = bh & 7;
    const size_t obase = ((size_t)b * HID + h * DHEAD) * LSEQ + q0;
#pragma unroll
    for (int it = tid; it < 2048; it += 256) {
        int d = it >> 5, c = (it & 31) * 4;
        float4 v = *(float4*)&Ot[d * POT + c];
        u32 h0, l0, h1, l1;
        split_pair(v.x, v.y, h0, l0);
        split_pair(v.z, v.w, h1, l1);
        size_t off = obase + (size_t)d * LSEQ + c;
        *(uint2*)(g_ath + off) = make_uint2(h0, h1);
        *(uint2*)(g_atl + off) = make_uint2(l0, l1);
    }
}

// ---------------------------------------------------------------------------
extern "C" void kernel_launch(void* const* d_in, const int* in_sizes, int n_in,
                              void* d_out, int out_size)
{
    const float* x     = (const float*)d_in[0];
    const float* w_qkv = (const float*)d_in[1];
    const float* w_out = (const float*)d_in[2];
    const float* b_out = (const float*)d_in[3];
    float* out = (float*)d_out;

    float* qkv;
    uint16_t *xh, *xl, *wqh, *wql, *woh, *wol, *ath, *atl;
    cudaGetSymbolAddress((void**)&qkv, g_qkv);
    cudaGetSymbolAddress((void**)&xh,  g_xh);
    cudaGetSymbolAddress((void**)&xl,  g_xl);
    cudaGetSymbolAddress((void**)&wqh, g_wqh);
    cudaGetSymbolAddress((void**)&wql, g_wql);
    cudaGetSymbolAddress((void**)&woh, g_woh);
    cudaGetSymbolAddress((void**)&wol, g_wol);
    cudaGetSymbolAddress((void**)&ath, g_ath);
    cudaGetSymbolAddress((void**)&atl, g_atl);

    cudaFuncSetAttribute(gemm_bfp,
        cudaFuncAttributeMaxDynamicSharedMemorySize, GEMM_SMEM);
    cudaFuncSetAttribute(flash_mma,
        cudaFuncAttributeMaxDynamicSharedMemorySize, FLASH_SMEM);

    dim3 t(256);

    // 0) pre-split all GEMM operands to bf16 hi/lo
    split_scale<<<(B_ * CDIM * LSEQ / 4) / 256, t>>>(x, xh, xl,
        B_ * CDIM * LSEQ / 4, 0);
    split_scale<<<(O3 * CDIM / 4) / 256, t>>>(w_qkv, wqh, wql,
        O3 * CDIM / 4, HID * CDIM / 4);          // q rows pre-scaled
    split_scale<<<(CDIM * HID / 4) / 256, t>>>(w_out, woh, wol,
        CDIM * HID / 4, 0);

    // 1) qkv = w_qkv @ x (fp32 out for conv kernels)
    gemm_bfp<<<dim3(LSEQ / 128, O3 / 128, B_), t, GEMM_SMEM>>>(
        wqh, wql, xh, xl, qkv, nullptr, LSEQ, CDIM,
        (long)CDIM * LSEQ, (long)O3 * LSEQ);

    // 2) flash-layout bf16 conversions
    conv_qk<<<dim3(LSEQ / 64, B_ * HEADS_, 2), t>>>(qkv);
    conv_v<<<dim3((B_ * HID * LSEQ) / (256 * 4)), t>>>(qkv);

    // 3) flash attention (outputs bf16 hi/lo att)
    flash_mma<<<dim3(LSEQ / 128, B_ * HEADS_), t, FLASH_SMEM>>>();

    // 4) out = w_out @ att + b_out
    gemm_bfp<<<dim3(LSEQ / 128, CDIM / 128, B_), t, GEMM_SMEM>>>(
        woh, wol, ath, atl, out, b_out, LSEQ, HID,
        (long)HID * LSEQ, (long)CDIM * LSEQ);
}